// round 7
// baseline (speedup 1.0000x reference)
#include <cuda_runtime.h>
#include <math.h>

#define Bv 32
#define Sv 2048
#define Ev 1024
#define Dv 1024

// Scratch (no device allocations)
__device__ float g_pp [Bv * 128];          // hp partials per (batch, itile)
__device__ float g_qp [16][Bv * Ev];       // q partials per d-chunk
__device__ float g_c  [Bv];
__device__ float g_p  [Bv];
__device__ float g_att[Bv * Sv];
__device__ int   g_cnt[Bv];                // zero-init; self-resetting

__device__ __forceinline__ float warp_sum(float v) {
#pragma unroll
    for (int o = 16; o > 0; o >>= 1) v += __shfl_xor_sync(0xffffffffu, v, o);
    return v;
}
__device__ __forceinline__ float warp_max(float v) {
#pragma unroll
    for (int o = 16; o > 0; o >>= 1) v = fmaxf(v, __shfl_xor_sync(0xffffffffu, v, o));
    return v;
}

// ---------------------------------------------------------------------------
// k_hp (side stream): warp per i, 8 batches per block, 512 blocks.
// Partial vp·tanh(Wp h + b) sums per (b, itile) -> g_pp.
// ---------------------------------------------------------------------------
__global__ void k_hp(const float* __restrict__ h,
                     const float* __restrict__ Wp_w,
                     const float* __restrict__ Wp_b,
                     const float* __restrict__ vp_w) {
    __shared__ float4 hs4[8][Dv / 4];     // 32 KB
    __shared__ float wtmp[8][8];
    int t = threadIdx.x;
    int b0 = (blockIdx.x >> 7) * 8;
    int itile = blockIdx.x & 127;
    for (int idx = t; idx < 8 * (Dv / 4); idx += 256) {
        int k = idx >> 8, j = idx & 255;
        hs4[k][j] = ((const float4*)(h + (size_t)(b0 + k) * Dv))[j];
    }
    __syncthreads();
    int w = t >> 5, lane = t & 31;
    int i = itile * 8 + w;
    const float4* wr = (const float4*)(Wp_w + (size_t)i * Dv);
    float acc[8];
#pragma unroll
    for (int k = 0; k < 8; k++) acc[k] = 0.f;
#pragma unroll
    for (int j = lane; j < Dv / 4; j += 32) {
        float4 wv = wr[j];
#pragma unroll
        for (int k = 0; k < 8; k++) {
            float4 x = hs4[k][j];
            acc[k] += wv.x * x.x + wv.y * x.y + wv.z * x.z + wv.w * x.w;
        }
    }
#pragma unroll
    for (int k = 0; k < 8; k++) acc[k] = warp_sum(acc[k]);
    if (lane == 0) {
        float bia = Wp_b[i];
        float vp  = vp_w[i];
#pragma unroll
        for (int k = 0; k < 8; k++) wtmp[w][k] = tanhf(acc[k] + bia) * vp;
    }
    __syncthreads();
    if (t < 8) {
        float s = 0.f;
#pragma unroll
        for (int w2 = 0; w2 < 8; w2++) s += wtmp[w2][t];
        g_pp[(b0 + t) * 128 + itile] = s;
    }
}

// k_p (side stream, after k_hp): finalize p[b]. One warp per batch.
__global__ void k_p(const float* __restrict__ vp_b) {
    int wrp = threadIdx.x >> 5, lane = threadIdx.x & 31;
    int b = wrp;
    const float* pp = g_pp + b * 128;
    float s = pp[lane] + pp[lane + 32] + pp[lane + 64] + pp[lane + 96];
    s = warp_sum(s);
    if (lane == 0) {
        float x = s + vp_b[0];
        g_p[b] = (float)Sv / (1.f + expf(-x));
    }
}

// ---------------------------------------------------------------------------
// k_q: 160 blocks. [0,128): q partials (row-major Wa_w). [128,160): c[b].
// ---------------------------------------------------------------------------
__global__ void k_q(const float* __restrict__ h,
                    const float* __restrict__ Wa_w,
                    const float* __restrict__ Wa_b) {
    int bid = blockIdx.x, t = threadIdx.x;
    if (bid < 128) {
        __shared__ float hs[4][64];
        int dc = bid >> 3;
        int bg = bid & 7;
        int b0 = bg * 4, d0 = dc * 64;
        if (t < 256) {
            int k = t >> 6, d = t & 63;
            hs[k][d] = h[(size_t)(b0 + k) * Dv + d0 + d];
        }
        __syncthreads();
        float4 a0 = make_float4(0.f,0.f,0.f,0.f), a1 = a0, a2 = a0, a3 = a0;
#pragma unroll 4
        for (int d = 0; d < 64; d++) {
            float4 wv = ((const float4*)(Wa_w + (size_t)(d0 + d) * Ev))[t];
            float x0 = hs[0][d], x1 = hs[1][d], x2 = hs[2][d], x3 = hs[3][d];
            a0.x += wv.x*x0; a0.y += wv.y*x0; a0.z += wv.z*x0; a0.w += wv.w*x0;
            a1.x += wv.x*x1; a1.y += wv.y*x1; a1.z += wv.z*x1; a1.w += wv.w*x1;
            a2.x += wv.x*x2; a2.y += wv.y*x2; a2.z += wv.z*x2; a2.w += wv.w*x2;
            a3.x += wv.x*x3; a3.y += wv.y*x3; a3.z += wv.z*x3; a3.w += wv.w*x3;
        }
        ((float4*)(g_qp[dc] + (b0 + 0) * Ev))[t] = a0;
        ((float4*)(g_qp[dc] + (b0 + 1) * Ev))[t] = a1;
        ((float4*)(g_qp[dc] + (b0 + 2) * Ev))[t] = a2;
        ((float4*)(g_qp[dc] + (b0 + 3) * Ev))[t] = a3;
    } else {
        int b = bid - 128;
        float v = 0.f;
        for (int d = t; d < Dv; d += 256) v += h[b * Dv + d] * Wa_b[d];
        v = warp_sum(v);
        __shared__ float red[8];
        if ((t & 31) == 0) red[t >> 5] = v;
        __syncthreads();
        if (t == 0) {
            float s = 0.f;
#pragma unroll
            for (int i = 0; i < 8; i++) s += red[i];
            g_c[b] = s;
        }
    }
}

// ---------------------------------------------------------------------------
// k_att: grid (32 tiles, 32 batches), 256 threads.
//   att for 64 s rows, then the LAST block of each batch (atomic counter)
//   finalizes: softmax stats + alpha + windowed awe. No k_fin node.
// ---------------------------------------------------------------------------
__global__ void k_att(const float* __restrict__ enc, float* __restrict__ awe,
                      float* __restrict__ alpha) {
    __shared__ float4 qs[Ev / 4];
    int tile = blockIdx.x, b = blockIdx.y, t = threadIdx.x;

    // q = sum of 16 d-chunk partials (L2-hot)
    for (int j = t; j < Ev; j += 256) {
        float s = 0.f;
#pragma unroll
        for (int dc = 0; dc < 16; dc++) s += g_qp[dc][b * Ev + j];
        ((float*)qs)[j] = s;
    }
    __syncthreads();

    int w = t >> 5, lane = t & 31;
    float c = g_c[b];
#pragma unroll
    for (int r = 0; r < 8; r += 2) {
        int s = tile * 64 + w * 8 + r;
        const float4* er0 = (const float4*)(enc + ((size_t)b * Sv + s)     * Ev);
        const float4* er1 = (const float4*)(enc + ((size_t)b * Sv + s + 1) * Ev);
        float acc0 = 0.f, acc1 = 0.f;
#pragma unroll
        for (int j = lane; j < Ev / 4; j += 32) {
            float4 x  = qs[j];
            float4 a0 = __ldcs(er0 + j);
            float4 a1 = __ldcs(er1 + j);
            acc0 += a0.x * x.x + a0.y * x.y + a0.z * x.z + a0.w * x.w;
            acc1 += a1.x * x.x + a1.y * x.y + a1.z * x.z + a1.w * x.w;
        }
        acc0 = warp_sum(acc0);
        acc1 = warp_sum(acc1);
        if (lane == 0) {
            g_att[b * Sv + s]     = acc0 + c;
            g_att[b * Sv + s + 1] = acc1 + c;
        }
    }

    // ---- last-block-per-batch finalization ----
    __threadfence();
    __shared__ int slast;
    if (t == 0) slast = (atomicAdd(&g_cnt[b], 1) == 31);
    __syncthreads();
    if (!slast) return;
    __threadfence();
    if (t == 0) g_cnt[b] = 0;             // reset for next graph replay

    __shared__ float red[32];
    __shared__ float fin;
    __shared__ float aw[128];

    float p = g_p[b];
    int lo = (int)floorf(p) - 64;
    if (lo < 0) lo = 0;
    if (lo > Sv - 128) lo = Sv - 128;

    // softmax stats over 2048 values, 8 per thread (L2-hot)
    float av[8];
    float m = -1e30f;
#pragma unroll
    for (int i = 0; i < 8; i++) {
        av[i] = g_att[b * Sv + i * 256 + t];
        m = fmaxf(m, av[i]);
    }
    m = warp_max(m);
    if (lane == 0) red[w] = m;
    __syncthreads();
    if (w == 0) {
        float v = (lane < 8) ? red[lane] : -1e30f;
        v = warp_max(v);
        if (lane == 0) fin = v;
    }
    __syncthreads();
    float mb = fin;
    float l = 0.f;
#pragma unroll
    for (int i = 0; i < 8; i++) { av[i] = expf(av[i] - mb); l += av[i]; }
    l = warp_sum(l);
    __syncthreads();
    if (lane == 0) red[w] = l;
    __syncthreads();
    if (w == 0) {
        float v = (lane < 8) ? red[lane] : 0.f;
        v = warp_sum(v);
        if (lane == 0) fin = v;
    }
    __syncthreads();
    float inv = 1.f / fin;

    // alpha + window cache
#pragma unroll
    for (int i = 0; i < 8; i++) {
        int s = i * 256 + t;
        float d = (float)s - p;
        float al = av[i] * inv * expf(-d * d * 0.125f);
        alpha[b * Sv + s] = al;
        int wo = s - lo;
        if ((unsigned)wo < 128u) aw[wo] = al;
    }
    __syncthreads();

    // windowed awe: thread t owns float4-column t across all 128 window rows.
    // alpha outside |s-p|<=29 is exactly 0 (fp32 underflow, identical in the
    // reference) -> skip those loads.
    float4 acc = make_float4(0.f, 0.f, 0.f, 0.f);
    const float4* base = (const float4*)(enc + ((size_t)b * Sv + lo) * Ev);
#pragma unroll 8
    for (int sl = 0; sl < 128; sl++) {
        float a = aw[sl];
        if (a != 0.f) {
            float4 v = base[(size_t)sl * (Ev / 4) + t];
            acc.x += v.x * a; acc.y += v.y * a; acc.z += v.z * a; acc.w += v.w * a;
        }
    }
    ((float4*)(awe + b * Ev))[t] = acc;
}

extern "C" void kernel_launch(void* const* d_in, const int* in_sizes, int n_in,
                              void* d_out, int out_size) {
    const float* enc  = (const float*)d_in[0];   // [B,S,E]
    const float* h    = (const float*)d_in[1];   // [B,D]
    const float* Wa_w = (const float*)d_in[3];   // [D,E]
    const float* Wa_b = (const float*)d_in[4];   // [D]
    const float* Wp_w = (const float*)d_in[5];   // [D,D]
    const float* Wp_b = (const float*)d_in[6];   // [D]
    const float* vp_w = (const float*)d_in[7];   // [1,D]
    const float* vp_b = (const float*)d_in[8];   // [1]

    float* awe   = (float*)d_out;                 // [B,E]
    float* alpha = (float*)d_out + Bv * Ev;       // [B,S]

    // Fork: k_hp -> k_p on side stream, concurrent with k_q.
    // Join BEFORE k_att (its last blocks consume g_p).
    cudaStream_t s1;
    cudaStreamCreateWithFlags(&s1, cudaStreamNonBlocking);
    cudaEvent_t evFork, evJoin;
    cudaEventCreateWithFlags(&evFork, cudaEventDisableTiming);
    cudaEventCreateWithFlags(&evJoin, cudaEventDisableTiming);

    cudaEventRecord(evFork, 0);
    cudaStreamWaitEvent(s1, evFork, 0);

    k_hp<<<512, 256, 0, s1>>>(h, Wp_w, Wp_b, vp_w);   // side stream
    k_p <<<1, 1024, 0, s1>>>(vp_b);                   // side stream

    k_q <<<160, 256>>>(h, Wa_w, Wa_b);                // main stream

    cudaEventRecord(evJoin, s1);
    cudaStreamWaitEvent(0, evJoin, 0);

    k_att<<<dim3(32, Bv), 256>>>(enc, awe, alpha);    // includes finalization
}

// round 8
// speedup vs baseline: 1.0955x; 1.0955x over previous
#include <cuda_runtime.h>
#include <math.h>

#define Bv 32
#define Sv 2048
#define Ev 1024
#define Dv 1024

// Scratch (no device allocations, no atomics)
__device__ float g_pp [Bv * 128];          // hp partials per (batch, itile)
__device__ float g_qp4[4][Bv * Ev];        // q partials: 4 d-chunks
__device__ float g_c  [Bv];
__device__ float g_att[Bv * Sv];

__device__ __forceinline__ float warp_sum(float v) {
#pragma unroll
    for (int o = 16; o > 0; o >>= 1) v += __shfl_xor_sync(0xffffffffu, v, o);
    return v;
}
__device__ __forceinline__ float warp_max(float v) {
#pragma unroll
    for (int o = 16; o > 0; o >>= 1) v = fmaxf(v, __shfl_xor_sync(0xffffffffu, v, o));
    return v;
}

// ---------------------------------------------------------------------------
// k_pre: 672 blocks, single wave.
//   [0,512)    hp: warp per i, 8 batches/block -> g_pp (vp·tanh partials)
//   [512,640)  q : (e-tile 128) x (d-chunk 256) x (8 batches) -> g_qp4[dc]
//   [640,672)  c[b] = h[b]·Wa_b
// ---------------------------------------------------------------------------
__global__ void k_pre(const float* __restrict__ h,
                      const float* __restrict__ Wa_w,
                      const float* __restrict__ Wa_b,
                      const float* __restrict__ Wp_w,
                      const float* __restrict__ Wp_b,
                      const float* __restrict__ vp_w) {
    __shared__ float4 sbuf[2560];          // 40 KB, aliased per path
    int bid = blockIdx.x, t = threadIdx.x;

    if (bid < 512) {
        // ---- hp path ----
        float4 (*hs4)[Dv / 4] = (float4(*)[Dv / 4])sbuf;   // 32 KB
        __shared__ float wtmp[8][8];
        int b0 = (bid >> 7) * 8;
        int itile = bid & 127;
        for (int idx = t; idx < 8 * (Dv / 4); idx += 256) {
            int k = idx >> 8, j = idx & 255;
            hs4[k][j] = ((const float4*)(h + (size_t)(b0 + k) * Dv))[j];
        }
        __syncthreads();
        int w = t >> 5, lane = t & 31;
        int i = itile * 8 + w;
        const float4* wr = (const float4*)(Wp_w + (size_t)i * Dv);
        float acc[8];
#pragma unroll
        for (int k = 0; k < 8; k++) acc[k] = 0.f;
#pragma unroll
        for (int j = lane; j < Dv / 4; j += 32) {
            float4 wv = wr[j];
#pragma unroll
            for (int k = 0; k < 8; k++) {
                float4 x = hs4[k][j];
                acc[k] += wv.x * x.x + wv.y * x.y + wv.z * x.z + wv.w * x.w;
            }
        }
#pragma unroll
        for (int k = 0; k < 8; k++) acc[k] = warp_sum(acc[k]);
        if (lane == 0) {
            float bia = Wp_b[i];
            float vp  = vp_w[i];
#pragma unroll
            for (int k = 0; k < 8; k++) wtmp[w][k] = tanhf(acc[k] + bia) * vp;
        }
        __syncthreads();
        if (t < 8) {
            float s = 0.f;
#pragma unroll
            for (int w2 = 0; w2 < 8; w2++) s += wtmp[w2][t];
            g_pp[(b0 + t) * 128 + itile] = s;
        }
    } else if (bid < 640) {
        // ---- q path ----
        int id = bid - 512;                // 0..127
        int et = id & 7;                   // e-tile of 128 floats
        int dc = (id >> 3) & 3;            // d-chunk of 256 rows
        int bg = id >> 5;                  // 4 groups of 8 batches
        int b0 = bg * 8, d0 = dc * 256, e0 = et * 128;
        float*  hs  = (float*)sbuf;        // [8][256] = 8 KB
        float4* red = sbuf + 512;          // [8 dg][8 k][32 col] = 32 KB
        for (int idx = t; idx < 8 * 256; idx += 256) {
            int k = idx >> 8, d = idx & 255;
            hs[k * 256 + d] = h[(size_t)(b0 + k) * Dv + d0 + d];
        }
        __syncthreads();
        int col = t & 31, dg = t >> 5;     // 8 d-groups of 32 rows
        float4 acc[8];
#pragma unroll
        for (int k = 0; k < 8; k++) acc[k] = make_float4(0.f, 0.f, 0.f, 0.f);
#pragma unroll 4
        for (int i = 0; i < 32; i++) {
            int d = dg * 32 + i;
            float4 wv = ((const float4*)(Wa_w + (size_t)(d0 + d) * Ev + e0))[col];
#pragma unroll
            for (int k = 0; k < 8; k++) {
                float x = hs[k * 256 + d];
                acc[k].x += wv.x * x; acc[k].y += wv.y * x;
                acc[k].z += wv.z * x; acc[k].w += wv.w * x;
            }
        }
#pragma unroll
        for (int k = 0; k < 8; k++) red[(dg * 8 + k) * 32 + col] = acc[k];
        __syncthreads();
#pragma unroll
        for (int o = 4; o > 0; o >>= 1) {
            if (dg < o) {
#pragma unroll
                for (int k = 0; k < 8; k++) {
                    float4 u = red[(dg * 8 + k) * 32 + col];
                    float4 v = red[((dg + o) * 8 + k) * 32 + col];
                    u.x += v.x; u.y += v.y; u.z += v.z; u.w += v.w;
                    red[(dg * 8 + k) * 32 + col] = u;
                }
            }
            __syncthreads();
        }
        if (dg == 0) {
#pragma unroll
            for (int k = 0; k < 8; k++)
                ((float4*)(g_qp4[dc] + (size_t)(b0 + k) * Ev + e0))[col] =
                    red[k * 32 + col];
        }
    } else {
        // ---- c path ----
        int b = bid - 640;
        float v = 0.f;
        for (int d = t; d < Dv; d += 256) v += h[b * Dv + d] * Wa_b[d];
        v = warp_sum(v);
        __shared__ float redc[8];
        if ((t & 31) == 0) redc[t >> 5] = v;
        __syncthreads();
        if (t == 0) {
            float s = 0.f;
#pragma unroll
            for (int i = 0; i < 8; i++) s += redc[i];
            g_c[b] = s;
        }
    }
}

// ---------------------------------------------------------------------------
// k_att: grid (32 tiles, 32 batches), 256 threads. Cheap 4-partial q reduce,
// then att for 64 s rows (2 rows per warp-iteration, streaming loads).
// ---------------------------------------------------------------------------
__global__ void k_att(const float* __restrict__ enc) {
    __shared__ float4 qs[Ev / 4];
    int tile = blockIdx.x, b = blockIdx.y, t = threadIdx.x;

    {   // q = sum of 4 d-chunk partials: one float4 per thread
        float4 s0 = ((const float4*)(g_qp4[0] + b * Ev))[t];
        float4 s1 = ((const float4*)(g_qp4[1] + b * Ev))[t];
        float4 s2 = ((const float4*)(g_qp4[2] + b * Ev))[t];
        float4 s3 = ((const float4*)(g_qp4[3] + b * Ev))[t];
        float4 r;
        r.x = (s0.x + s1.x) + (s2.x + s3.x);
        r.y = (s0.y + s1.y) + (s2.y + s3.y);
        r.z = (s0.z + s1.z) + (s2.z + s3.z);
        r.w = (s0.w + s1.w) + (s2.w + s3.w);
        qs[t] = r;
    }
    __syncthreads();

    int w = t >> 5, lane = t & 31;
    float c = g_c[b];
#pragma unroll
    for (int r = 0; r < 8; r += 2) {
        int s = tile * 64 + w * 8 + r;
        const float4* er0 = (const float4*)(enc + ((size_t)b * Sv + s)     * Ev);
        const float4* er1 = (const float4*)(enc + ((size_t)b * Sv + s + 1) * Ev);
        float acc0 = 0.f, acc1 = 0.f;
#pragma unroll
        for (int j = lane; j < Ev / 4; j += 32) {
            float4 x  = qs[j];
            float4 a0 = __ldcs(er0 + j);
            float4 a1 = __ldcs(er1 + j);
            acc0 += a0.x * x.x + a0.y * x.y + a0.z * x.z + a0.w * x.w;
            acc1 += a1.x * x.x + a1.y * x.y + a1.z * x.z + a1.w * x.w;
        }
        acc0 = warp_sum(acc0);
        acc1 = warp_sum(acc1);
        if (lane == 0) {
            g_att[b * Sv + s]     = acc0 + c;
            g_att[b * Sv + s + 1] = acc1 + c;
        }
    }
}

// ---------------------------------------------------------------------------
// k_fin: grid (8 e-tiles, 32 batches), 1024 threads.
//   p from g_pp + softmax stats (redundant per tile, L2-hot); tile 0 writes
//   alpha; each block computes a 128-col slice of awe over a 64-row window
//   (branchless — gauss is exactly 0 outside, identical to the reference).
// ---------------------------------------------------------------------------
__global__ void k_fin(const float* __restrict__ enc, float* __restrict__ awe,
                      float* __restrict__ alpha, const float* __restrict__ vp_b) {
    int tile = blockIdx.x, b = blockIdx.y, t = threadIdx.x;
    int lane = t & 31, wrp = t >> 5;
    __shared__ float red[128];
    __shared__ float fin, shp;
    __shared__ float aw[64];
    __shared__ float4 pacc[32][32];        // 16 KB

    // p[b] from 128 hp partials
    if (t < 128) red[t] = g_pp[b * 128 + t];
    __syncthreads();
    for (int o = 64; o > 0; o >>= 1) {
        if (t < o) red[t] += red[t + o];
        __syncthreads();
    }
    if (t == 0) {
        float x = red[0] + vp_b[0];
        shp = (float)Sv / (1.f + expf(-x));
    }
    __syncthreads();
    float p = shp;
    int lo = (int)floorf(p) - 31;
    if (lo < 0) lo = 0;
    if (lo > Sv - 64) lo = Sv - 64;

    // softmax stats
    float a0 = g_att[b * Sv + t];
    float a1 = g_att[b * Sv + t + 1024];
    float m = warp_max(fmaxf(a0, a1));
    if (lane == 0) red[wrp] = m;
    __syncthreads();
    if (wrp == 0) {
        float v = warp_max(red[lane]);
        if (lane == 0) fin = v;
    }
    __syncthreads();
    float mb = fin;
    float e0 = expf(a0 - mb), e1 = expf(a1 - mb);
    float l = warp_sum(e0 + e1);
    __syncthreads();
    if (lane == 0) red[wrp] = l;
    __syncthreads();
    if (wrp == 0) {
        float v = warp_sum(red[lane]);
        if (lane == 0) fin = v;
    }
    __syncthreads();
    float inv = 1.f / fin;
    float d0 = (float)t - p, d1 = (float)(t + 1024) - p;
    float al0 = e0 * inv * expf(-d0 * d0 * 0.125f);
    float al1 = e1 * inv * expf(-d1 * d1 * 0.125f);
    if (tile == 0) {
        alpha[b * Sv + t]        = al0;
        alpha[b * Sv + t + 1024] = al1;
    }
    int w0 = t - lo, w1 = t + 1024 - lo;
    if ((unsigned)w0 < 64u) aw[w0] = al0;
    if ((unsigned)w1 < 64u) aw[w1] = al1;
    __syncthreads();

    // windowed awe slice: 64 rows x 128 cols, branchless
    int col = t & 31;                      // float4 col within the slice
    int rg  = t >> 5;                      // 32 row-groups of 2 rows
    const float4* base = (const float4*)(enc + ((size_t)b * Sv + lo) * Ev)
                         + tile * 32;
    float4 acc = make_float4(0.f, 0.f, 0.f, 0.f);
#pragma unroll
    for (int i = 0; i < 2; i++) {
        int sl = rg * 2 + i;
        float a = aw[sl];
        float4 v = base[(size_t)sl * (Ev / 4) + col];
        acc.x += v.x * a; acc.y += v.y * a; acc.z += v.z * a; acc.w += v.w * a;
    }
    pacc[rg][col] = acc;
    __syncthreads();
#pragma unroll
    for (int o = 16; o > 0; o >>= 1) {
        if (rg < o) {
            float4 u = pacc[rg][col], v = pacc[rg + o][col];
            u.x += v.x; u.y += v.y; u.z += v.z; u.w += v.w;
            pacc[rg][col] = u;
        }
        __syncthreads();
    }
    if (t < 32)
        ((float4*)(awe + b * Ev + tile * 128))[t] = pacc[0][t];
}

extern "C" void kernel_launch(void* const* d_in, const int* in_sizes, int n_in,
                              void* d_out, int out_size) {
    const float* enc  = (const float*)d_in[0];   // [B,S,E]
    const float* h    = (const float*)d_in[1];   // [B,D]
    const float* Wa_w = (const float*)d_in[3];   // [D,E]
    const float* Wa_b = (const float*)d_in[4];   // [D]
    const float* Wp_w = (const float*)d_in[5];   // [D,D]
    const float* Wp_b = (const float*)d_in[6];   // [D]
    const float* vp_w = (const float*)d_in[7];   // [1,D]
    const float* vp_b = (const float*)d_in[8];   // [1]

    float* awe   = (float*)d_out;                 // [B,E]
    float* alpha = (float*)d_out + Bv * Ev;       // [B,S]

    k_pre<<<672, 256>>>(h, Wa_w, Wa_b, Wp_w, Wp_b, vp_w);
    k_att<<<dim3(32, Bv), 256>>>(enc);
    k_fin<<<dim3(8, Bv), 1024>>>(enc, awe, alpha, vp_b);
}